// round 1
// baseline (speedup 1.0000x reference)
#include <cuda_runtime.h>
#include <cuda_bf16.h>

#define N_   2
#define C_   256
#define T_   16
#define H_   56
#define W_   56
#define K_   5
#define OUT_ 16
#define CH   32           // channels per block

#define ROI_ELEMS  (N_*T_*K_*C_*OUT_*OUT_)   // 10,485,760
#define FEAT_ELEMS (N_*C_*T_*H_*W_)          // 25,690,112

__global__ void __launch_bounds__(256)
roi_align_kernel(const float* __restrict__ feat,
                 const float* __restrict__ rois,
                 float* __restrict__ out)
{
    const int tile = blockIdx.x;           // ((n*T + t)*K + k)
    const int k  = tile % K_;
    const int nt = tile / K_;
    const int t  = nt % T_;
    const int n  = nt / T_;
    const int c0 = blockIdx.y * CH;

    const int tid = threadIdx.x;           // 0..255 -> (py, px)
    const int px  = tid & 15;
    const int py  = tid >> 4;

    // Box for (n, k): rois layout (N, K, 5), cols 1..4 = xyxy
    const float* r = rois + (n * K_ + k) * 5;
    const float x1 = r[1] * 0.0625f - 0.5f;
    const float y1 = r[2] * 0.0625f - 0.5f;
    const float x2 = r[3] * 0.0625f - 0.5f;
    const float y2 = r[4] * 0.0625f - 0.5f;
    const float bw = (x2 - x1) * (1.0f / OUT_);
    const float bh = (y2 - y1) * (1.0f / OUT_);

    // Precompute 4 samples x 4 taps: offsets + weights (independent of c, t)
    int   off[4][4];
    float wgt[4][4];
    #pragma unroll
    for (int s = 0; s < 4; s++) {
        const float gx = (s & 1) ? 0.75f : 0.25f;
        const float gy = (s >> 1) ? 0.75f : 0.25f;
        const float X = x1 + ((float)px + gx) * bw;
        const float Y = y1 + ((float)py + gy) * bh;
        const bool valid = (Y > -1.0f) && (Y < (float)H_) &&
                           (X > -1.0f) && (X < (float)W_);
        const float Xc = fminf(fmaxf(X, 0.0f), (float)(W_ - 1));
        const float Yc = fminf(fmaxf(Y, 0.0f), (float)(H_ - 1));
        const int x0i = (int)floorf(Xc);
        const int y0i = (int)floorf(Yc);
        const int x1i = min(x0i + 1, W_ - 1);
        const int y1i = min(y0i + 1, H_ - 1);
        const float lx = Xc - (float)x0i;
        const float ly = Yc - (float)y0i;
        const float hx = 1.0f - lx;
        const float hy = 1.0f - ly;
        const float m  = valid ? 1.0f : 0.0f;
        off[s][0] = y0i * W_ + x0i;
        off[s][1] = y0i * W_ + x1i;
        off[s][2] = y1i * W_ + x0i;
        off[s][3] = y1i * W_ + x1i;
        wgt[s][0] = hy * hx * m;
        wgt[s][1] = hy * lx * m;
        wgt[s][2] = ly * hx * m;
        wgt[s][3] = ly * lx * m;
    }

    // Output: (n, t, k, c, py, px) row-major; tid is the last 256 elems.
    size_t outbase = ((size_t)tile * C_ + c0) * (OUT_ * OUT_) + tid;
    const float* fb = feat + (((size_t)(n * C_ + c0) * T_ + t) * (size_t)(H_ * W_));

    #pragma unroll 4
    for (int c = 0; c < CH; c++) {
        const float* f = fb + (size_t)c * (T_ * H_ * W_);
        float acc = 0.0f;
        #pragma unroll
        for (int s = 0; s < 4; s++) {
            acc += wgt[s][0] * __ldg(f + off[s][0])
                 + wgt[s][1] * __ldg(f + off[s][1])
                 + wgt[s][2] * __ldg(f + off[s][2])
                 + wgt[s][3] * __ldg(f + off[s][3]);
        }
        out[outbase + (size_t)c * (OUT_ * OUT_)] = acc * 0.25f;
    }
}

extern "C" void kernel_launch(void* const* d_in, const int* in_sizes, int n_in,
                              void* d_out, int out_size)
{
    const float* feat = (const float*)d_in[0];
    const float* rois = (const float*)d_in[1];
    float* out = (float*)d_out;

    // RoIAlign into first ROI_ELEMS floats of d_out
    dim3 grid(N_ * T_ * K_, C_ / CH);
    roi_align_kernel<<<grid, 256>>>(feat, rois, out);

    // feat passthrough into the tail of d_out (copy engine / capturable)
    cudaMemcpyAsync(out + ROI_ELEMS, feat,
                    (size_t)FEAT_ELEMS * sizeof(float),
                    cudaMemcpyDeviceToDevice, 0);
}

// round 8
// speedup vs baseline: 1.5036x; 1.5036x over previous
#include <cuda_runtime.h>
#include <cuda_bf16.h>

#define N_   2
#define C_   256
#define T_   16
#define H_   56
#define W_   56
#define K_   5
#define OUT_ 16

#define CH   16            // channels per roi block
#define PH   20            // patch rows  (max footprint: 15.5*1.133 + 2 < 20)
#define PW   20            // patch cols
#define PWP  21            // padded row stride (bank spread)

#define ROI_ELEMS  (N_*T_*K_*C_*OUT_*OUT_)   // 10,485,760
#define FEAT_ELEMS (N_*C_*T_*H_*W_)          // 25,690,112

#define NTILE      (N_*T_*K_)                // 160
#define NCGRP      (C_/CH)                   // 16
#define NROI_BLKS  (NTILE*NCGRP)             // 2560
#define NCOPY_BLKS 1536
#define NTOT_BLKS  (NROI_BLKS + NCOPY_BLKS)  // 4096  (8-block groups: 5 roi + 3 copy)

__global__ void __launch_bounds__(256)
fused_roi_copy_kernel(const float* __restrict__ feat,
                      const float* __restrict__ rois,
                      float* __restrict__ out)
{
    __shared__ float patch[CH][PH][PWP];     // 26.9 KB

    const int b   = blockIdx.x;
    const int grp = b >> 3;
    const int lb  = b & 7;
    const int tid = threadIdx.x;

    if (lb >= 5) {
        // ---------------- copy role: feat -> out tail, float4 grid-stride ----
        const int cb = grp * 3 + (lb - 5);                    // 0..NCOPY_BLKS-1
        const float4* __restrict__ src = (const float4*)feat;
        float4* __restrict__ dst = (float4*)(out + ROI_ELEMS);
        const int n4 = FEAT_ELEMS / 4;                        // 6,422,528
        for (int i = cb * 256 + tid; i < n4; i += NCOPY_BLKS * 256)
            dst[i] = src[i];
        return;
    }

    // ------------------- roi role -------------------------------------------
    const int rb   = grp * 5 + lb;            // 0..NROI_BLKS-1
    const int cgrp = rb & (NCGRP - 1);
    const int tile = rb >> 4;                  // ((n*T + t)*K + k)
    const int k  = tile % K_;
    const int nt = tile / K_;
    const int t  = nt % T_;
    const int n  = nt / T_;
    const int c0 = cgrp * CH;

    const int px = tid & 15;
    const int py = tid >> 4;

    // Box (same for every thread; broadcast loads)
    const float* r = rois + (n * K_ + k) * 5;
    const float x1 = r[1] * 0.0625f - 0.5f;
    const float y1 = r[2] * 0.0625f - 0.5f;
    const float x2 = r[3] * 0.0625f - 0.5f;
    const float y2 = r[4] * 0.0625f - 0.5f;
    const float bw = (x2 - x1) * (1.0f / OUT_);
    const float bh = (y2 - y1) * (1.0f / OUT_);

    // Patch origin (uniform across block): floor of the clamped min sample coord
    const float Xmin = fminf(fmaxf(x1 + 0.25f * bw, 0.0f), (float)(W_ - 1));
    const float Ymin = fminf(fmaxf(y1 + 0.25f * bh, 0.0f), (float)(H_ - 1));
    const int x_lo = (int)floorf(Xmin);
    const int y_lo = (int)floorf(Ymin);

    // ---- cooperative staging: CH channels x PH x PW, coalesced, clamped ----
    {
        const float* fb = feat + (((size_t)(n * C_ + c0) * T_ + t) * (size_t)(H_ * W_));
        for (int i = tid; i < CH * PH * PW; i += 256) {
            const int c  = i / (PH * PW);
            const int rr = i - c * (PH * PW);
            const int yy = rr / PW;
            const int xx = rr - yy * PW;
            const int gy = min(y_lo + yy, H_ - 1);
            const int gx = min(x_lo + xx, W_ - 1);
            patch[c][yy][xx] = __ldg(fb + (size_t)c * (T_ * H_ * W_) + gy * W_ + gx);
        }
    }

    // ---- per-thread sample offsets/weights (relative to patch) -------------
    int   off[4][4];
    float wgt[4][4];
    #pragma unroll
    for (int s = 0; s < 4; s++) {
        const float gx = (s & 1) ? 0.75f : 0.25f;
        const float gy = (s >> 1) ? 0.75f : 0.25f;
        const float X = x1 + ((float)px + gx) * bw;
        const float Y = y1 + ((float)py + gy) * bh;
        const bool valid = (Y > -1.0f) && (Y < (float)H_) &&
                           (X > -1.0f) && (X < (float)W_);
        const float Xc = fminf(fmaxf(X, 0.0f), (float)(W_ - 1));
        const float Yc = fminf(fmaxf(Y, 0.0f), (float)(H_ - 1));
        const int x0i = (int)floorf(Xc);
        const int y0i = (int)floorf(Yc);
        const int x1i = min(x0i + 1, W_ - 1);
        const int y1i = min(y0i + 1, H_ - 1);
        const float lx = Xc - (float)x0i;
        const float ly = Yc - (float)y0i;
        const float hx = 1.0f - lx;
        const float hy = 1.0f - ly;
        const float m  = valid ? 0.25f : 0.0f;   // fold the /4 sample mean in
        const int ry0 = y0i - y_lo, ry1 = y1i - y_lo;
        const int rx0 = x0i - x_lo, rx1 = x1i - x_lo;
        off[s][0] = ry0 * PWP + rx0;
        off[s][1] = ry0 * PWP + rx1;
        off[s][2] = ry1 * PWP + rx0;
        off[s][3] = ry1 * PWP + rx1;
        wgt[s][0] = hy * hx * m;
        wgt[s][1] = hy * lx * m;
        wgt[s][2] = ly * hx * m;
        wgt[s][3] = ly * lx * m;
    }

    __syncthreads();

    // ---- compute: 16 LDS + 16 FFMA per channel -----------------------------
    size_t outbase = ((size_t)tile * C_ + c0) * (OUT_ * OUT_) + tid;
    #pragma unroll 2
    for (int c = 0; c < CH; c++) {
        const float* p = &patch[c][0][0];
        float acc = 0.0f;
        #pragma unroll
        for (int s = 0; s < 4; s++) {
            acc += wgt[s][0] * p[off[s][0]]
                 + wgt[s][1] * p[off[s][1]]
                 + wgt[s][2] * p[off[s][2]]
                 + wgt[s][3] * p[off[s][3]];
        }
        out[outbase + (size_t)c * (OUT_ * OUT_)] = acc;
    }
}

extern "C" void kernel_launch(void* const* d_in, const int* in_sizes, int n_in,
                              void* d_out, int out_size)
{
    const float* feat = (const float*)d_in[0];
    const float* rois = (const float*)d_in[1];
    float* out = (float*)d_out;

    fused_roi_copy_kernel<<<NTOT_BLKS, 256>>>(feat, rois, out);
}